// round 9
// baseline (speedup 1.0000x reference)
#include <cuda_runtime.h>
#include <math.h>

#define H 1024
#define S 32768
#define NBLOCK 148
#define NTHREAD 1024
#define NWARP 32
#define GWARPS (NBLOCK * NWARP)          // 4736 warps
#define NPAIR (S / 2)                    // 16384 row pairs
#define NF4 (S / 4)                      // 8192 output float4s

// Scratch (no allocations allowed in kernel_launch)
__device__ __align__(16) float g_v[H];
__device__ __align__(16) float g_scores[S];
__device__ __align__(16) float g_pmax[NBLOCK];
__device__ __align__(16) float g_psum[NBLOCK];

// Grid barrier: counters self-reset, epoch flags monotonic -> graph-replay safe.
__device__ unsigned g_cnt[2];
__device__ unsigned g_flag[2];

__device__ __forceinline__ void grid_bar(int i) {
    __syncthreads();
    if (threadIdx.x == 0) {
        volatile unsigned* flag = &g_flag[i];
        unsigned snap = *flag;
        __threadfence();
        unsigned pos = atomicAdd(&g_cnt[i], 1u);
        if (pos == NBLOCK - 1) {
            g_cnt[i] = 0;
            __threadfence();
            atomicAdd(&g_flag[i], 1u);
        } else {
            while (*flag == snap) { __nanosleep(64); }
        }
        __threadfence();
    }
    __syncthreads();
}

__global__ __launch_bounds__(NTHREAD, 1)
void k_all(const float* __restrict__ hidden,
           const float* __restrict__ enc,
           const float* __restrict__ W,
           float* __restrict__ out) {
    __shared__ float  ph1[33 * 32];     // phase-1 partials (padded)
    __shared__ float4 sv[H / 4];        // v staged for scores
    __shared__ float  sm[NWARP], ss[NWARP];
    __shared__ float  sh[2];

    const int b    = blockIdx.x;
    const int t    = threadIdx.x;
    const int warp = t >> 5;
    const int lane = t & 31;

    // ---------------- Phase 1: v = hidden @ W  (32 blocks) --------------------
    if (b < 32) {
        const int h0 = b * 32;
        float acc = 0.0f;
#pragma unroll 8
        for (int j = 0; j < 32; j++) {
            const int d = warp * 32 + j;
            acc = fmaf(__ldg(&hidden[d]), __ldg(&W[(size_t)d * H + h0 + lane]), acc);
        }
        ph1[warp * 33 + lane] = acc;
        __syncthreads();
        if (t < 32) {
            float v = 0.0f;
#pragma unroll
            for (int dgi = 0; dgi < 32; dgi++) v += ph1[dgi * 33 + t];
            g_v[h0 + t] = v;
        }
    }

    grid_bar(0);

    // ---------------- Phase 2: scores, 2 rows per warp-iteration --------------
    if (t < H / 4) sv[t] = reinterpret_cast<const float4*>(g_v)[t];
    __syncthreads();

    const int gwarp = b * NWARP + warp;
    float ra[8];                         // per-row final scores (all lanes)
#pragma unroll
    for (int j = 0; j < 8; j++) ra[j] = -INFINITY;

#pragma unroll 1
    for (int it = 0; it < 4; it++) {
        const int p = it * GWARPS + gwarp;          // pair index
        if (p >= NPAIR) break;
        const float4* e0 = reinterpret_cast<const float4*>(enc + (size_t)(2 * p)     * H);
        const float4* e1 = reinterpret_cast<const float4*>(enc + (size_t)(2 * p + 1) * H);
        float a0 = 0.0f, a1 = 0.0f;
#pragma unroll
        for (int i = 0; i < 8; i++) {
            const int idx = lane + 32 * i;
            float4 x0 = __ldg(&e0[idx]);
            float4 x1 = __ldg(&e1[idx]);
            float4 w  = sv[idx];
            a0 = fmaf(x0.x, w.x, a0); a1 = fmaf(x1.x, w.x, a1);
            a0 = fmaf(x0.y, w.y, a0); a1 = fmaf(x1.y, w.y, a1);
            a0 = fmaf(x0.z, w.z, a0); a1 = fmaf(x1.z, w.z, a1);
            a0 = fmaf(x0.w, w.w, a0); a1 = fmaf(x1.w, w.w, a1);
        }
#pragma unroll
        for (int off = 16; off > 0; off >>= 1) {
            a0 += __shfl_xor_sync(0xFFFFFFFFu, a0, off);
            a1 += __shfl_xor_sync(0xFFFFFFFFu, a1, off);
        }
        if (lane == 0)
            reinterpret_cast<float2*>(g_scores)[p] = make_float2(a0, a1);
        ra[2 * it]     = a0;
        ra[2 * it + 1] = a1;
    }

    // warp stats from registers (identical on all lanes; no shuffles needed)
    {
        float m = ra[0];
#pragma unroll
        for (int j = 1; j < 8; j++) m = fmaxf(m, ra[j]);
        float s = 0.0f;
#pragma unroll
        for (int j = 0; j < 8; j++) s += __expf(ra[j] - m);   // exp(-inf)=0
        if (lane == 0) { sm[warp] = m; ss[warp] = s; }
    }
    __syncthreads();

    if (warp == 0) {
        float wm = sm[lane], wsum = ss[lane];
        float gm = wm;
#pragma unroll
        for (int off = 16; off > 0; off >>= 1)
            gm = fmaxf(gm, __shfl_xor_sync(0xFFFFFFFFu, gm, off));
        float e = wsum * __expf(wm - gm);
#pragma unroll
        for (int off = 16; off > 0; off >>= 1)
            e += __shfl_xor_sync(0xFFFFFFFFu, e, off);
        if (lane == 0) { g_pmax[b] = gm; g_psum[b] = e; }
    }

    grid_bar(1);

    // ---------------- Phase 3: redundant combine (148 pairs) + normalize ------
    if (warp == 0) {
        float lsum = 0.0f;
        float pm[5], psv[5];
#pragma unroll
        for (int j = 0; j < 5; j++) {
            const int idx = lane + 32 * j;
            const bool ok = idx < NBLOCK;
            pm[j]  = ok ? g_pmax[idx] : -INFINITY;
            psv[j] = ok ? g_psum[idx] : 0.0f;
        }
        float gm = pm[0];
#pragma unroll
        for (int j = 1; j < 5; j++) gm = fmaxf(gm, pm[j]);
#pragma unroll
        for (int off = 16; off > 0; off >>= 1)
            gm = fmaxf(gm, __shfl_xor_sync(0xFFFFFFFFu, gm, off));
#pragma unroll
        for (int j = 0; j < 5; j++)
            lsum = fmaf(psv[j], __expf(pm[j] - gm), lsum);
#pragma unroll
        for (int off = 16; off > 0; off >>= 1)
            lsum += __shfl_xor_sync(0xFFFFFFFFu, lsum, off);
        if (lane == 0) { sh[0] = gm; sh[1] = 1.0f / lsum; }
    }
    __syncthreads();
    const float gmax = sh[0], inv = sh[1];

    const unsigned s0 = ((unsigned)b * NF4) / NBLOCK;
    const unsigned s1 = ((unsigned)(b + 1) * NF4) / NBLOCK;
    const unsigned i  = s0 + t;
    if (i < s1) {
        float4 sc = reinterpret_cast<const float4*>(g_scores)[i];
        float4 o;
        o.x = __expf(sc.x - gmax) * inv;
        o.y = __expf(sc.y - gmax) * inv;
        o.z = __expf(sc.z - gmax) * inv;
        o.w = __expf(sc.w - gmax) * inv;
        reinterpret_cast<float4*>(out)[i] = o;
    }
}

// ---------------------------------------------------------------------------
// Inputs: hidden[1024], encoder_outputs[32768*1024], W[1024*1024], b[1024]
// (b cancels in softmax). Output: float[32768].
// ---------------------------------------------------------------------------
extern "C" void kernel_launch(void* const* d_in, const int* in_sizes, int n_in,
                              void* d_out, int out_size) {
    const float* hidden = (const float*)d_in[0];
    const float* enc    = (const float*)d_in[1];
    const float* W      = (const float*)d_in[2];
    float* out          = (float*)d_out;

    k_all<<<NBLOCK, NTHREAD>>>(hidden, enc, W, out);
}

// round 10
// speedup vs baseline: 1.0727x; 1.0727x over previous
#include <cuda_runtime.h>
#include <math.h>

#define H 1024
#define S 32768
#define NBLOCK 296                       // 2 CTAs per SM
#define NTHREAD 512
#define NWARP 16
#define GWARPS (NBLOCK * NWARP)          // 4736 warps
#define NF4 (S / 4)                      // 8192 output float4s

// Scratch (no allocations allowed in kernel_launch)
__device__ __align__(16) float g_v[H];
__device__ __align__(16) float g_scores[S];
__device__ __align__(16) float g_pmax[NBLOCK];
__device__ __align__(16) float g_psum[NBLOCK];

// Grid barrier: counters self-reset, epoch flags monotonic -> graph-replay safe.
__device__ unsigned g_cnt[2];
__device__ unsigned g_flag[2];

__device__ __forceinline__ void grid_bar(int i) {
    __syncthreads();
    if (threadIdx.x == 0) {
        volatile unsigned* flag = &g_flag[i];
        unsigned snap = *flag;
        __threadfence();
        unsigned pos = atomicAdd(&g_cnt[i], 1u);
        if (pos == NBLOCK - 1) {
            g_cnt[i] = 0;
            __threadfence();
            atomicAdd(&g_flag[i], 1u);
        } else {
            while (*flag == snap) { __nanosleep(64); }
        }
        __threadfence();
    }
    __syncthreads();
}

__global__ __launch_bounds__(NTHREAD, 2)
void k_all(const float* __restrict__ hidden,
           const float* __restrict__ enc,
           const float* __restrict__ W,
           float* __restrict__ out) {
    __shared__ float  ph1[16 * 33];     // phase-1 partials (padded)
    __shared__ float4 sv[H / 4];        // v staged for scores (4 KB)
    __shared__ float  sm[NWARP], ss[NWARP];
    __shared__ float  sh[2];

    const int b    = blockIdx.x;
    const int t    = threadIdx.x;
    const int warp = t >> 5;
    const int lane = t & 31;

    // ---------------- Phase 1: v = hidden @ W  (32 blocks) --------------------
    // block b<32 owns h-range [b*32, b*32+32); warp dg owns 64 d's.
    if (b < 32) {
        const int h0 = b * 32;
        float acc = 0.0f;
#pragma unroll 8
        for (int j = 0; j < 64; j++) {
            const int d = warp * 64 + j;
            acc = fmaf(__ldg(&hidden[d]), __ldg(&W[(size_t)d * H + h0 + lane]), acc);
        }
        ph1[warp * 33 + lane] = acc;
        __syncthreads();
        if (t < 32) {
            float v = 0.0f;
#pragma unroll
            for (int dgi = 0; dgi < 16; dgi++) v += ph1[dgi * 33 + t];
            g_v[h0 + t] = v;
        }
    }

    grid_bar(0);

    // ---------------- Phase 2: scores, 1 row per warp-iteration ---------------
    if (t < H / 4) sv[t] = reinterpret_cast<const float4*>(g_v)[t];
    __syncthreads();

    const int gwarp = b * NWARP + warp;
    float ra[7];
#pragma unroll
    for (int j = 0; j < 7; j++) ra[j] = -INFINITY;

#pragma unroll 1
    for (int it = 0; it < 7; it++) {
        const int row = it * GWARPS + gwarp;
        if (row >= S) break;
        const float4* erow = reinterpret_cast<const float4*>(enc + (size_t)row * H);
        float acc = 0.0f;
#pragma unroll
        for (int i = 0; i < 8; i++) {
            const int idx = lane + 32 * i;
            float4 e = __ldg(&erow[idx]);
            float4 w = sv[idx];
            acc = fmaf(e.x, w.x, acc);
            acc = fmaf(e.y, w.y, acc);
            acc = fmaf(e.z, w.z, acc);
            acc = fmaf(e.w, w.w, acc);
        }
#pragma unroll
        for (int off = 16; off > 0; off >>= 1)
            acc += __shfl_xor_sync(0xFFFFFFFFu, acc, off);
        if (lane == 0) g_scores[row] = acc;
        ra[it] = acc;                    // all lanes hold full sum after butterfly
    }

    // warp stats from registers (identical on all lanes)
    {
        float m = ra[0];
#pragma unroll
        for (int j = 1; j < 7; j++) m = fmaxf(m, ra[j]);
        float s = 0.0f;
#pragma unroll
        for (int j = 0; j < 7; j++) s += __expf(ra[j] - m);   // exp(-inf)=0
        if (lane == 0) { sm[warp] = m; ss[warp] = s; }
    }
    __syncthreads();

    if (warp == 0 && lane < NWARP) {
        float wm = sm[lane], wsum = ss[lane];
        float gm = wm;
#pragma unroll
        for (int off = 8; off > 0; off >>= 1)
            gm = fmaxf(gm, __shfl_xor_sync(0x0000FFFFu, gm, off));
        float e = wsum * __expf(wm - gm);
#pragma unroll
        for (int off = 8; off > 0; off >>= 1)
            e += __shfl_xor_sync(0x0000FFFFu, e, off);
        if (lane == 0) { g_pmax[b] = gm; g_psum[b] = e; }
    }

    grid_bar(1);

    // ---------------- Phase 3: redundant combine (296 pairs) + normalize ------
    if (warp == 0) {
        float lsum = 0.0f;
        float pm[10], psv[10];
#pragma unroll
        for (int j = 0; j < 10; j++) {
            const int idx = lane + 32 * j;
            const bool ok = idx < NBLOCK;
            pm[j]  = ok ? g_pmax[idx] : -INFINITY;
            psv[j] = ok ? g_psum[idx] : 0.0f;
        }
        float gm = pm[0];
#pragma unroll
        for (int j = 1; j < 10; j++) gm = fmaxf(gm, pm[j]);
#pragma unroll
        for (int off = 16; off > 0; off >>= 1)
            gm = fmaxf(gm, __shfl_xor_sync(0xFFFFFFFFu, gm, off));
#pragma unroll
        for (int j = 0; j < 10; j++)
            lsum = fmaf(psv[j], __expf(pm[j] - gm), lsum);
#pragma unroll
        for (int off = 16; off > 0; off >>= 1)
            lsum += __shfl_xor_sync(0xFFFFFFFFu, lsum, off);
        if (lane == 0) { sh[0] = gm; sh[1] = 1.0f / lsum; }
    }
    __syncthreads();
    const float gmax = sh[0], inv = sh[1];

    // contiguous per-block slice of the 8192 output float4s (~28 per block)
    const unsigned s0 = ((unsigned)b * NF4) / NBLOCK;
    const unsigned s1 = ((unsigned)(b + 1) * NF4) / NBLOCK;
    const unsigned i  = s0 + t;
    if (i < s1) {
        float4 sc = reinterpret_cast<const float4*>(g_scores)[i];
        float4 o;
        o.x = __expf(sc.x - gmax) * inv;
        o.y = __expf(sc.y - gmax) * inv;
        o.z = __expf(sc.z - gmax) * inv;
        o.w = __expf(sc.w - gmax) * inv;
        reinterpret_cast<float4*>(out)[i] = o;
    }
}

// ---------------------------------------------------------------------------
// Inputs: hidden[1024], encoder_outputs[32768*1024], W[1024*1024], b[1024]
// (b cancels in softmax). Output: float[32768].
// ---------------------------------------------------------------------------
extern "C" void kernel_launch(void* const* d_in, const int* in_sizes, int n_in,
                              void* d_out, int out_size) {
    const float* hidden = (const float*)d_in[0];
    const float* enc    = (const float*)d_in[1];
    const float* W      = (const float*)d_in[2];
    float* out          = (float*)d_out;

    k_all<<<NBLOCK, NTHREAD>>>(hidden, enc, W, out);
}